// round 15
// baseline (speedup 1.0000x reference)
#include <cuda_runtime.h>
#include <cuda_bf16.h>
#include <cuda_fp16.h>
#include <math.h>
#include <cstdint>

// Problem constants
#define TZc 512
#define Bc  64
#define Hc  512
#define Ec  256
#define Vc  3000
#define Dc  5
#define VTc 3512          // V + TZ
#define GINc 1285         // E + 2H + D
#define XPADc 1288
#define G3c 1536          // 3H
#define ENC_ELEMS 16777216  // 32768*512
#define SPN (64u * 512u * 3512u)   // 115,081,216 sparse elements

// ---------------- scratch (device globals; no allocation allowed) ------------
__device__ float g_accbuf[5 * 32768];
__device__ float g_hw[2 * 32768];
__device__ float g_x[Bc * XPADc];
__device__ float g_gi[Bc * G3c];
__device__ float g_gh[Bc * G3c];
__device__ float g_h1[Bc * Hc];
__device__ float g_ecs[Bc * TZc];
__device__ float g_mrow[Bc];
__device__ float g_zc[32768 * 512];
__device__ float g_ppart[4 * 64 * 3008];   // proj partials [jc][b][v]
__device__ float g_zpart[64 * 8 * 3520];   // zcopy partials [b][tc][v]
__device__ float g_wih[G3c * XPADc];
__device__ __half g_sparse_h[SPN];         // fp16 copy of sparse (230MB)
__device__ __nv_bfloat16 g_wt_hi[3 * 512 * 512];
__device__ __nv_bfloat16 g_wt_lo[3 * 512 * 512];
__device__ __nv_bfloat16 g_enc_hi[2 * ENC_ELEMS];
__device__ __nv_bfloat16 g_enc_lo[2 * ENC_ELEMS];

// ---------------- streams/events (created pre-main, before harness checkpoints)
struct StreamsInit {
    cudaStream_t s1, s2, s3;
    cudaEvent_t ev_root, ev_prepw, ev_encz, ev_encu, ev_h1, ev_zc, ev_proj, ev_sparse;
    StreamsInit() {
        cudaStreamCreateWithFlags(&s1, cudaStreamNonBlocking);
        cudaStreamCreateWithFlags(&s2, cudaStreamNonBlocking);
        cudaStreamCreateWithFlags(&s3, cudaStreamNonBlocking);
        cudaEventCreateWithFlags(&ev_root, cudaEventDisableTiming);
        cudaEventCreateWithFlags(&ev_prepw, cudaEventDisableTiming);
        cudaEventCreateWithFlags(&ev_encz, cudaEventDisableTiming);
        cudaEventCreateWithFlags(&ev_encu, cudaEventDisableTiming);
        cudaEventCreateWithFlags(&ev_h1, cudaEventDisableTiming);
        cudaEventCreateWithFlags(&ev_zc, cudaEventDisableTiming);
        cudaEventCreateWithFlags(&ev_proj, cudaEventDisableTiming);
        cudaEventCreateWithFlags(&ev_sparse, cudaEventDisableTiming);
    }
};
static StreamsInit g_sx;

// ---------------- helpers ------------------------------------------------------
__device__ __forceinline__ float tanh_fast(float x) {
    float y;
    asm("tanh.approx.f32 %0, %1;" : "=f"(y) : "f"(x));
    return y;
}
__device__ __forceinline__ void mma16816(float* c, const uint32_t* a, const uint32_t* b) {
    asm volatile(
        "mma.sync.aligned.m16n8k16.row.col.f32.bf16.bf16.f32 "
        "{%0,%1,%2,%3}, {%4,%5,%6,%7}, {%8,%9}, {%0,%1,%2,%3};"
        : "+f"(c[0]), "+f"(c[1]), "+f"(c[2]), "+f"(c[3])
        : "r"(a[0]), "r"(a[1]), "r"(a[2]), "r"(a[3]), "r"(b[0]), "r"(b[1]));
}
__device__ __forceinline__ uint32_t smem_u32(const void* p) {
    uint32_t a;
    asm("{ .reg .u64 t; cvta.to.shared.u64 t, %1; cvt.u32.u64 %0, t; }" : "=r"(a) : "l"(p));
    return a;
}
__device__ __forceinline__ void ldsm_x4(uint32_t& r0, uint32_t& r1, uint32_t& r2,
                                        uint32_t& r3, uint32_t addr) {
    asm volatile("ldmatrix.sync.aligned.m8n8.x4.shared.b16 {%0,%1,%2,%3}, [%4];"
                 : "=r"(r0), "=r"(r1), "=r"(r2), "=r"(r3) : "r"(addr));
}
__device__ __forceinline__ void cpasync16(uint32_t dst, const void* src) {
    asm volatile("cp.async.cg.shared.global [%0], [%1], 16;" :: "r"(dst), "l"(src));
}

// ---------------- block reductions -------------------------------------------
__device__ __forceinline__ float blockReduceMax(float v, float* sh) {
    #pragma unroll
    for (int o = 16; o; o >>= 1) v = fmaxf(v, __shfl_xor_sync(0xffffffffu, v, o));
    if ((threadIdx.x & 31) == 0) sh[threadIdx.x >> 5] = v;
    __syncthreads();
    float r = sh[0];
    int nw = (blockDim.x + 31) >> 5;
    for (int j = 1; j < nw; j++) r = fmaxf(r, sh[j]);
    __syncthreads();
    return r;
}
__device__ __forceinline__ float blockReduceSum(float v, float* sh) {
    #pragma unroll
    for (int o = 16; o; o >>= 1) v += __shfl_xor_sync(0xffffffffu, v, o);
    if ((threadIdx.x & 31) == 0) sh[threadIdx.x >> 5] = v;
    __syncthreads();
    float r = 0.f;
    int nw = (blockDim.x + 31) >> 5;
    for (int j = 0; j < nw; j++) r += sh[j];
    __syncthreads();
    return r;
}

// ---------------- kernels -----------------------------------------------------

__global__ void k_zero() {
    int i = blockIdx.x * blockDim.x + threadIdx.x;
    if (i < 4 * 32768) g_accbuf[i] = 0.f;
}

__global__ void k_prep_w(const float* __restrict__ Wz, const float* __restrict__ Wu,
                         const float* __restrict__ Wc2) {
    __shared__ float ts[32][33];
    int which = blockIdx.z;
    const float* W = (which == 0) ? (Wz + 512 * 512) : (which == 1) ? (Wu + 512 * 512) : Wc2;
    int k0 = blockIdx.y * 32, n0 = blockIdx.x * 32;
    int tx = threadIdx.x, ty = threadIdx.y;
    #pragma unroll
    for (int j = 0; j < 32; j += 8)
        ts[ty + j][tx] = W[(size_t)(k0 + ty + j) * 512 + n0 + tx];
    __syncthreads();
    __nv_bfloat16* oh = g_wt_hi + (size_t)which * 262144;
    __nv_bfloat16* ol = g_wt_lo + (size_t)which * 262144;
    #pragma unroll
    for (int j = 0; j < 32; j += 8) {
        float x = ts[tx][ty + j];
        __nv_bfloat16 h = __float2bfloat16(x);
        __nv_bfloat16 l = __float2bfloat16(x - __bfloat162float(h));
        size_t idx = (size_t)(n0 + ty + j) * 512 + k0 + tx;
        oh[idx] = h; ol[idx] = l;
    }
}

// 8 elems/thread, 16B stores; `which` selects destination slot
__global__ void __launch_bounds__(256)
k_prep_enc(const float* __restrict__ src, int which) {
    size_t i8 = (size_t)blockIdx.x * 256 + threadIdx.x;   // 8-elem unit, < 2097152
    const float4* s4 = (const float4*)src + i8 * 2;
    float4 v0 = s4[0], v1 = s4[1];
    float xs[8] = {v0.x, v0.y, v0.z, v0.w, v1.x, v1.y, v1.z, v1.w};
    union { uint4 u; __nv_bfloat16 h[8]; } ph, pl;
    #pragma unroll
    for (int j = 0; j < 8; j++) {
        __nv_bfloat16 hh = __float2bfloat16(xs[j]);
        ph.h[j] = hh;
        pl.h[j] = __float2bfloat16(xs[j] - __bfloat162float(hh));
    }
    ((uint4*)(g_enc_hi + (size_t)which * ENC_ELEMS))[i8] = ph.u;
    ((uint4*)(g_enc_lo + (size_t)which * ENC_ELEMS))[i8] = pl.u;
}

// sparse fp32 -> fp16, 8 elems/thread (SPN = 14385152 * 8 exactly)
__global__ void __launch_bounds__(256)
k_prep_sparse(const float* __restrict__ sparse) {
    size_t i8 = (size_t)blockIdx.x * 256 + threadIdx.x;
    if (i8 >= SPN / 8) return;
    const float4* s4 = (const float4*)sparse + i8 * 2;
    float4 v0 = s4[0], v1 = s4[1];
    union { uint4 u; __half2 h[4]; } p;
    p.h[0] = __floats2half2_rn(v0.x, v0.y);
    p.h[1] = __floats2half2_rn(v0.z, v0.w);
    p.h[2] = __floats2half2_rn(v1.x, v1.y);
    p.h[3] = __floats2half2_rn(v1.z, v1.w);
    ((uint4*)g_sparse_h)[i8] = p.u;
}

__global__ void k_prep_wih(const float* __restrict__ W_ih) {
    int g = blockIdx.x;
    for (int i = threadIdx.x; i < XPADc; i += 256)
        g_wih[(size_t)g * XPADc + i] = (i < GINc) ? W_ih[(size_t)g * GINc + i] : 0.f;
}

__global__ void k_hW(const float* __restrict__ h0,
                     const float* __restrict__ Wz, const float* __restrict__ bz,
                     const float* __restrict__ Wu, const float* __restrict__ bu) {
    int b = blockIdx.x, which = blockIdx.y, k = threadIdx.x;
    const float* W  = which ? Wu : Wz;
    const float* bb = which ? bu : bz;
    float* o = g_hw + which * 32768;
    __shared__ float sh[512];
    sh[k] = h0[b * 512 + k];
    __syncthreads();
    float acc = bb[k];
    #pragma unroll 8
    for (int j = 0; j < 512; j++) acc += sh[j] * W[j * 512 + k];
    o[b * 512 + k] = acc;
}

// ---------------- 2-stage pipelined mma.sync GEMM, warp tile 32x64 ------------
// grid: x = n-tile (4), y = m-tile (512), z = gemm offset; gid = gbase + z
#define SA_STRIDE 72
#define SMA (64 * SA_STRIDE)
#define SMB (128 * SA_STRIDE)
#define STG_ELEMS (2 * SMA + 2 * SMB)
#define STG_BYTES (STG_ELEMS * 2)
#define OFF_AH 0
#define OFF_AL SMA
#define OFF_BH (2 * SMA)
#define OFF_BL (2 * SMA + SMB)
#define GEMM_SMEM (2 * STG_BYTES)         // 110592 B
__global__ void __launch_bounds__(128, 2)
k_mma_gemm(const float* __restrict__ vz, const float* __restrict__ vu,
           const float* __restrict__ bc2, int gbase) {
    extern __shared__ char smem_raw[];
    const uint32_t sbase = smem_u32(smem_raw);

    const int tid = threadIdx.x;
    const int wid = tid >> 5;      // 0..3
    const int lane = tid & 31;
    const int gro = lane >> 2;
    const int tig = lane & 3;
    const int wm = wid >> 1;       // 0..1  (M, 32 rows)
    const int wn = wid & 1;        // 0..1  (N, 64 cols)

    const int gid = gbase + blockIdx.z;
    const int n0 = blockIdx.x * 128;
    const int m0 = blockIdx.y * 64;

    const size_t encoff = (gid == 1) ? (size_t)ENC_ELEMS : 0;
    const __nv_bfloat16* AH = g_enc_hi + encoff;
    const __nv_bfloat16* AL = g_enc_lo + encoff;
    const __nv_bfloat16* WtH = g_wt_hi + (size_t)gid * 262144;
    const __nv_bfloat16* WtL = g_wt_lo + (size_t)gid * 262144;

    const int a_row0 = wm * 32 + (lane & 7) + ((lane & 8) ? 8 : 0);
    const int a_koff = (lane & 16) ? 8 : 0;
    const int b_rowbase = wn * 64 + (lane & 7) + ((lane & 16) ? 8 : 0);
    const int b_koff = (lane & 8) ? 8 : 0;

    float c[2][8][4];
    #pragma unroll
    for (int mt = 0; mt < 2; mt++)
        #pragma unroll
        for (int i = 0; i < 8; i++)
            #pragma unroll
            for (int r = 0; r < 4; r++) c[mt][i][r] = 0.f;

    auto load_stage = [&](uint32_t sdst, int kk) {
        #pragma unroll
        for (int i = 0; i < 16; i++) {
            int idx = tid + i * 128;           // 0..2047 : B
            int buf = idx >> 10;
            int line = idx & 1023;
            int row = line >> 3, kq = line & 7;
            uint32_t dst = sdst + (uint32_t)((buf ? OFF_BL : OFF_BH) + row * SA_STRIDE + kq * 8) * 2;
            const __nv_bfloat16* src = (buf ? WtL : WtH) + (size_t)(n0 + row) * 512 + kk + kq * 8;
            cpasync16(dst, src);
        }
        #pragma unroll
        for (int i = 0; i < 8; i++) {
            int idx = tid + i * 128;           // 0..1023 : A
            int buf = idx >> 9;
            int line = idx & 511;
            int row = line >> 3, kq = line & 7;
            uint32_t dst = sdst + (uint32_t)((buf ? OFF_AL : OFF_AH) + row * SA_STRIDE + kq * 8) * 2;
            const __nv_bfloat16* src = (buf ? AL : AH) + (size_t)(m0 + row) * 512 + kk + kq * 8;
            cpasync16(dst, src);
        }
        asm volatile("cp.async.commit_group;");
    };

    load_stage(sbase, 0);
    asm volatile("cp.async.wait_group 0;");
    __syncthreads();

    for (int ck = 0; ck < 8; ck++) {
        const uint32_t scur = sbase + (uint32_t)(ck & 1) * STG_BYTES;
        const uint32_t snxt = sbase + (uint32_t)((ck & 1) ^ 1) * STG_BYTES;
        if (ck < 7) load_stage(snxt, (ck + 1) * 64);
        #pragma unroll
        for (int ks = 0; ks < 4; ks++) {
            uint32_t ah[2][4], al[2][4];
            #pragma unroll
            for (int mt = 0; mt < 2; mt++) {
                uint32_t aoff = (uint32_t)((a_row0 + mt * 16) * SA_STRIDE + ks * 16 + a_koff) * 2;
                ldsm_x4(ah[mt][0], ah[mt][1], ah[mt][2], ah[mt][3], scur + OFF_AH * 2 + aoff);
                ldsm_x4(al[mt][0], al[mt][1], al[mt][2], al[mt][3], scur + OFF_AL * 2 + aoff);
            }
            #pragma unroll
            for (int nt2 = 0; nt2 < 4; nt2++) {
                uint32_t boff = (uint32_t)((b_rowbase + nt2 * 16) * SA_STRIDE + ks * 16 + b_koff) * 2;
                uint32_t b0, b1, b2, b3;
                ldsm_x4(b0, b1, b2, b3, scur + OFF_BH * 2 + boff);
                uint32_t beh[2] = {b0, b1}, boh[2] = {b2, b3};
                #pragma unroll
                for (int mt = 0; mt < 2; mt++) {
                    mma16816(c[mt][nt2 * 2],     ah[mt], beh);
                    mma16816(c[mt][nt2 * 2 + 1], ah[mt], boh);
                    mma16816(c[mt][nt2 * 2],     al[mt], beh);
                    mma16816(c[mt][nt2 * 2 + 1], al[mt], boh);
                }
                ldsm_x4(b0, b1, b2, b3, scur + OFF_BL * 2 + boff);
                uint32_t bel[2] = {b0, b1}, bol[2] = {b2, b3};
                #pragma unroll
                for (int mt = 0; mt < 2; mt++) {
                    mma16816(c[mt][nt2 * 2],     ah[mt], bel);
                    mma16816(c[mt][nt2 * 2 + 1], ah[mt], bol);
                }
            }
        }
        if (ck < 7) asm volatile("cp.async.wait_group 0;");
        __syncthreads();
    }

    if (gid < 2) {
        const int t = blockIdx.y;
        const float* vv = gid ? vu : vz;
        #pragma unroll
        for (int mt = 0; mt < 2; mt++) {
            #pragma unroll
            for (int h = 0; h < 2; h++) {
                int b = wm * 32 + mt * 16 + gro + h * 8;
                const float* bias = g_hw + gid * 32768 + b * 512;
                float s = 0.f;
                #pragma unroll
                for (int nt = 0; nt < 8; nt++) {
                    #pragma unroll
                    for (int j = 0; j < 2; j++) {
                        int n = n0 + wn * 64 + nt * 8 + tig * 2 + j;
                        s += tanh_fast(c[mt][nt][h * 2 + j] + bias[n]) * vv[n];
                    }
                }
                s += __shfl_xor_sync(0xffffffffu, s, 1);
                s += __shfl_xor_sync(0xffffffffu, s, 2);
                if (tig == 0) atomicAdd(&g_accbuf[gid * 32768 + b * 512 + t], s);
            }
        }
    } else {
        float* zs = (float*)smem_raw;   // [64][130]
        #pragma unroll
        for (int mt = 0; mt < 2; mt++) {
            #pragma unroll
            for (int h = 0; h < 2; h++) {
                int r = wm * 32 + mt * 16 + gro + h * 8;
                #pragma unroll
                for (int nt = 0; nt < 8; nt++) {
                    #pragma unroll
                    for (int j = 0; j < 2; j++) {
                        int nl = wn * 64 + nt * 8 + tig * 2 + j;
                        zs[r * 130 + nl] = tanhf(c[mt][nt][h * 2 + j] + bc2[n0 + nl]);
                    }
                }
            }
        }
        __syncthreads();
        for (int i = tid; i < 64 * 32; i += 128) {
            int r = i >> 5, c4 = (i & 31) * 4;
            float4 v = make_float4(zs[r * 130 + c4], zs[r * 130 + c4 + 1],
                                   zs[r * 130 + c4 + 2], zs[r * 130 + c4 + 3]);
            *(float4*)(g_zc + (size_t)(m0 + r) * 512 + n0 + c4) = v;
        }
    }
}

// fused softmax + ctx
__global__ void k_ctx(const float* __restrict__ z_enc, const float* __restrict__ u_enc) {
    int which = blockIdx.z;
    int b  = blockIdx.y;
    int t0 = blockIdx.x * 64;
    int h  = threadIdx.x;
    const float* enc = which ? u_enc : z_enc;
    const float* e   = g_accbuf + which * 32768 + b * 512;
    float* ctx = g_accbuf + (2 + which) * 32768 + b * 512;
    __shared__ float shr[16];
    __shared__ float sa[64];
    float x = e[h];
    float m = blockReduceMax(x, shr);
    float ex = expf(x - m);
    float ssum = blockReduceSum(ex, shr);
    if (h >= t0 && h < t0 + 64) sa[h - t0] = ex / ssum;
    __syncthreads();
    float s = 0.f;
    #pragma unroll 8
    for (int tt = 0; tt < 64; tt++)
        s += sa[tt] * enc[((size_t)(t0 + tt) * 64 + b) * 512 + h];
    atomicAdd(&ctx[h], s);
}

__global__ void k_assemble(const float* __restrict__ emb, const int* __restrict__ mt,
                           const float* __restrict__ degree) {
    int b = blockIdx.x, tid = threadIdx.x;
    float* xr = g_x + b * XPADc;
    const float* ctxz = g_accbuf + 2 * 32768 + b * 512;
    const float* ctxu = g_accbuf + 3 * 32768 + b * 512;
    int m = mt[b];
    if (tid < 256) xr[tid] = emb[(size_t)m * Ec + tid];
    xr[256 + tid] = ctxu[tid];
    xr[768 + tid] = ctxz[tid];
    if (tid < 8) xr[1280 + tid] = (tid < 5) ? degree[b * Dc + tid] : 0.f;
}

__global__ void __launch_bounds__(256)
k_gates(const float* __restrict__ W_hh,
        const float* __restrict__ b_ih, const float* __restrict__ b_hh,
        const float* __restrict__ h0) {
    int b = threadIdx.x & 63;
    int g = blockIdx.x * 4 + (threadIdx.x >> 6);
    const float4* xr = (const float4*)(g_x + b * XPADc);
    const float4* wr = (const float4*)(g_wih + (size_t)g * XPADc);
    float a0 = 0.f, a1 = 0.f, a2 = 0.f, a3 = 0.f;
    #pragma unroll 2
    for (int j = 0; j < 320; j += 4) {
        float4 w0 = wr[j], x0 = xr[j];
        float4 w1 = wr[j+1], x1 = xr[j+1];
        float4 w2 = wr[j+2], x2 = xr[j+2];
        float4 w3 = wr[j+3], x3 = xr[j+3];
        a0 += w0.x*x0.x + w0.y*x0.y + w0.z*x0.z + w0.w*x0.w;
        a1 += w1.x*x1.x + w1.y*x1.y + w1.z*x1.z + w1.w*x1.w;
        a2 += w2.x*x2.x + w2.y*x2.y + w2.z*x2.z + w2.w*x2.w;
        a3 += w3.x*x3.x + w3.y*x3.y + w3.z*x3.z + w3.w*x3.w;
    }
    {
        float4 w0 = wr[320], x0 = xr[320];
        float4 w1 = wr[321], x1 = xr[321];
        a0 += w0.x*x0.x + w0.y*x0.y + w0.z*x0.z + w0.w*x0.w;
        a1 += w1.x*x1.x + w1.y*x1.y + w1.z*x1.z + w1.w*x1.w;
    }
    g_gi[b * G3c + g] = b_ih[g] + (a0 + a1) + (a2 + a3);

    const float4* hr = (const float4*)(h0 + b * 512);
    const float4* wh = (const float4*)(W_hh + (size_t)g * 512);
    a0 = a1 = a2 = a3 = 0.f;
    #pragma unroll 2
    for (int j = 0; j < 128; j += 4) {
        float4 w0 = wh[j], x0 = hr[j];
        float4 w1 = wh[j+1], x1 = hr[j+1];
        float4 w2 = wh[j+2], x2 = hr[j+2];
        float4 w3 = wh[j+3], x3 = hr[j+3];
        a0 += w0.x*x0.x + w0.y*x0.y + w0.z*x0.z + w0.w*x0.w;
        a1 += w1.x*x1.x + w1.y*x1.y + w1.z*x1.z + w1.w*x1.w;
        a2 += w2.x*x2.x + w2.y*x2.y + w2.z*x2.z + w2.w*x2.w;
        a3 += w3.x*x3.x + w3.y*x3.y + w3.z*x3.z + w3.w*x3.w;
    }
    g_gh[b * G3c + g] = b_hh[g] + (a0 + a1) + (a2 + a3);
}

__global__ void k_h1(const float* __restrict__ h0, float* __restrict__ out) {
    int b = blockIdx.x, h = threadIdx.x;
    float ir = g_gi[b * G3c + h],        hr = g_gh[b * G3c + h];
    float iz = g_gi[b * G3c + 512 + h],  hz = g_gh[b * G3c + 512 + h];
    float in_ = g_gi[b * G3c + 1024 + h], hn = g_gh[b * G3c + 1024 + h];
    float r = 1.f / (1.f + expf(-(ir + hr)));
    float z = 1.f / (1.f + expf(-(iz + hz)));
    float n = tanhf(in_ + r * hn);
    float hv = (1.f - z) * n + z * h0[b * 512 + h];
    g_h1[b * 512 + h] = hv;
    out[Bc * VTc + b * 512 + h] = hv;
    out[Bc * VTc + Bc * 512 + b * 512 + h] = hv;
}

__global__ void __launch_bounds__(256)
k_csdot() {
    int t = blockIdx.x;
    int q = threadIdx.x & 3;
    int b = threadIdx.x >> 2;
    const float4* zr = (const float4*)(g_zc + ((size_t)t * 64 + b) * 512);
    const float4* hr = (const float4*)(g_h1 + b * 512);
    float s = 0.f;
    #pragma unroll 8
    for (int i = 0; i < 32; i++) {
        int idx = i * 4 + q;
        float4 a = zr[idx], h = hr[idx];
        s += a.x * h.x + a.y * h.y + a.z * h.z + a.w * h.w;
    }
    s += __shfl_xor_sync(0xffffffffu, s, 1);
    s += __shfl_xor_sync(0xffffffffu, s, 2);
    if (q == 0) g_accbuf[4 * 32768 + b * 512 + t] = s;
}

__global__ void __launch_bounds__(128)
k_proj_part(const float* __restrict__ W_proj) {
    __shared__ float sx[16][385];
    int b0 = blockIdx.y * 16;
    int jc = blockIdx.z;
    int j0 = jc * 384;
    int tid = threadIdx.x;
    for (int i = tid; i < 16 * 384; i += 128) {
        int bl = i / 384, jj = i % 384;
        int j = j0 + jj;
        int b = b0 + bl;
        float v;
        if (j < 512)       v = g_accbuf[2 * 32768 + b * 512 + j];
        else if (j < 1024) v = g_accbuf[3 * 32768 + b * 512 + (j - 512)];
        else               v = g_h1[b * 512 + (j - 1024)];
        sx[bl][jj] = v;
    }
    __syncthreads();
    int v = blockIdx.x * 128 + tid;
    if (v >= Vc) return;
    float acc[16];
    #pragma unroll
    for (int bl = 0; bl < 16; bl++) acc[bl] = 0.f;
    #pragma unroll 4
    for (int jj = 0; jj < 384; jj++) {
        float w = W_proj[(size_t)(j0 + jj) * Vc + v];
        #pragma unroll
        for (int bl = 0; bl < 16; bl++) acc[bl] += sx[bl][jj] * w;
    }
    #pragma unroll
    for (int bl = 0; bl < 16; bl++)
        g_ppart[(size_t)(jc * 64 + b0 + bl) * 3008 + v] = acc[bl];
}

__global__ void k_rowmax() {
    __shared__ float sh[16];
    int b = blockIdx.x, t = threadIdx.x;
    float c = g_accbuf[4 * 32768 + b * 512 + t];
    float m = blockReduceMax(c, sh);
    g_ecs[b * 512 + t] = expf(c - m);
    if (t == 0) g_mrow[b] = m;
}

// zcopy partials from fp16 sparse: 8 values/thread, 439 uint4-lines per row
__global__ void __launch_bounds__(128)
k_zcopy_part() {
    __shared__ float se[64];
    int b = blockIdx.y, tc = blockIdx.z;
    int tid = threadIdx.x;
    if (tid < 64) se[tid] = g_ecs[b * 512 + tc * 64 + tid];
    __syncthreads();
    int v8 = blockIdx.x * 128 + tid;
    if (v8 >= 439) return;
    const uint4* sp = (const uint4*)(g_sparse_h + (size_t)b * TZc * VTc)
                      + (size_t)(tc * 64) * 439 + v8;
    float acc[8];
    #pragma unroll
    for (int j = 0; j < 8; j++) acc[j] = 0.f;
    #pragma unroll 4
    for (int t = 0; t < 64; t++) {
        union { uint4 u; __half2 h[4]; } x;
        x.u = sp[(size_t)t * 439];
        float e = se[t];
        #pragma unroll
        for (int j = 0; j < 4; j++) {
            float2 f = __half22float2(x.h[j]);
            acc[j * 2]     += e * f.x;
            acc[j * 2 + 1] += e * f.y;
        }
    }
    float* o = g_zpart + (size_t)(b * 8 + tc) * 3520 + v8 * 8;
    *(float4*)o       = make_float4(acc[0], acc[1], acc[2], acc[3]);
    *(float4*)(o + 4) = make_float4(acc[4], acc[5], acc[6], acc[7]);
}

__global__ void k_final(const float* __restrict__ b_proj, float* __restrict__ out) {
    __shared__ float sh[16];
    int b = blockIdx.x, tid = threadIdx.x;
    float gl[6], cl[7];
    #pragma unroll
    for (int i = 0; i < 6; i++) {
        int v = tid + i * 512;
        if (v < Vc) {
            float s = b_proj[v];
            #pragma unroll
            for (int jc = 0; jc < 4; jc++) s += g_ppart[(size_t)(jc * 64 + b) * 3008 + v];
            gl[i] = s;
        } else gl[i] = -1e30f;
    }
    float mb = g_mrow[b];
    #pragma unroll
    for (int i = 0; i < 7; i++) {
        int v = tid + i * 512;
        if (v < VTc) {
            float s = 0.f;
            #pragma unroll
            for (int tc = 0; tc < 8; tc++) s += g_zpart[(size_t)(b * 8 + tc) * 3520 + v];
            cl[i] = logf(s) + mb;
        } else cl[i] = -1e30f;
    }
    float m = -1e30f;
    #pragma unroll
    for (int i = 0; i < 6; i++) m = fmaxf(m, gl[i]);
    #pragma unroll
    for (int i = 0; i < 7; i++) m = fmaxf(m, cl[i]);
    m = blockReduceMax(m, sh);
    float s = 0.f;
    #pragma unroll
    for (int i = 0; i < 6; i++) s += expf(gl[i] - m);
    #pragma unroll
    for (int i = 0; i < 7; i++) s += expf(cl[i] - m);
    s = blockReduceSum(s, sh);
    float inv = 1.f / s;
    float* op = out + (size_t)b * VTc;
    #pragma unroll
    for (int i = 0; i < 7; i++) {
        int v = tid + i * 512;
        if (v < Vc)        op[v] = (expf(gl[i] - m) + expf(cl[i] - m)) * inv;
        else if (v < VTc)  op[v] = expf(cl[i] - m) * inv;
    }
}

// ---------------- launch ------------------------------------------------------
extern "C" void kernel_launch(void* const* d_in, const int* in_sizes, int n_in,
                              void* d_out, int out_size) {
    (void)in_sizes; (void)n_in; (void)out_size;
    const float* z_enc  = (const float*)d_in[0];
    const float* u_enc  = (const float*)d_in[1];
    const int*   mt     = (const int*)  d_in[2];
    const float* degree = (const float*)d_in[3];
    const float* h0     = (const float*)d_in[4];
    const float* sparse = (const float*)d_in[5];
    const float* emb    = (const float*)d_in[6];
    const float* Wz     = (const float*)d_in[7];
    const float* bz     = (const float*)d_in[8];
    const float* vz     = (const float*)d_in[9];
    const float* Wu     = (const float*)d_in[10];
    const float* bu     = (const float*)d_in[11];
    const float* vu     = (const float*)d_in[12];
    const float* W_ih   = (const float*)d_in[13];
    const float* W_hh   = (const float*)d_in[14];
    const float* b_ih   = (const float*)d_in[15];
    const float* b_hh   = (const float*)d_in[16];
    const float* W_proj = (const float*)d_in[17];
    const float* b_proj = (const float*)d_in[18];
    const float* Wc2    = (const float*)d_in[19];
    const float* bc2    = (const float*)d_in[20];
    float* out = (float*)d_out;

    cudaFuncSetAttribute(k_mma_gemm, cudaFuncAttributeMaxDynamicSharedMemorySize, GEMM_SMEM);

    // ---- fork root: side streams join capture via origin-stream event
    cudaEventRecord(g_sx.ev_root, 0);
    cudaStreamWaitEvent(g_sx.s1, g_sx.ev_root, 0);
    cudaStreamWaitEvent(g_sx.s2, g_sx.ev_root, 0);
    cudaStreamWaitEvent(g_sx.s3, g_sx.ev_root, 0);

    // s3: sparse fp32 -> fp16 (bandwidth overlapped with tensor-bound GEMMs)
    k_prep_sparse<<<56192, 256, 0, g_sx.s3>>>(sparse);
    cudaEventRecord(g_sx.ev_sparse, g_sx.s3);

    // default: weight transpose/split + hW
    k_prep_w<<<dim3(16, 16, 3), dim3(32, 8)>>>(Wz, Wu, Wc2);
    cudaEventRecord(g_sx.ev_prepw, 0);
    k_hW<<<dim3(Bc, 2), 512>>>(h0, Wz, bz, Wu, bu);
    // s1: encoder z split
    k_prep_enc<<<8192, 256, 0, g_sx.s1>>>(z_enc, 0);
    cudaEventRecord(g_sx.ev_encz, g_sx.s1);
    // s2: zero + wih repack + encoder u split
    k_zero<<<256, 512, 0, g_sx.s2>>>();
    k_prep_wih<<<G3c, 256, 0, g_sx.s2>>>(W_ih);
    k_prep_enc<<<8192, 256, 0, g_sx.s2>>>(u_enc, 1);
    cudaEventRecord(g_sx.ev_encu, g_sx.s2);

    // ---- zc gemm on s1 (needs enc_z + wt[2]) ----
    cudaStreamWaitEvent(g_sx.s1, g_sx.ev_prepw, 0);
    k_mma_gemm<<<dim3(4, 512, 1), 128, GEMM_SMEM, g_sx.s1>>>(vz, vu, bc2, 2);

    // ---- attention gemms + GRU chain on default ----
    cudaStreamWaitEvent(0, g_sx.ev_encz, 0);
    cudaStreamWaitEvent(0, g_sx.ev_encu, 0);
    k_mma_gemm<<<dim3(4, 512, 2), 128, GEMM_SMEM>>>(vz, vu, bc2, 0);
    k_ctx<<<dim3(8, Bc, 2), 512>>>(z_enc, u_enc);
    k_assemble<<<Bc, 512>>>(emb, mt, degree);
    k_gates<<<G3c / 4, 256>>>(W_hh, b_ih, b_hh, h0);
    k_h1<<<Bc, 512>>>(h0, out);
    cudaEventRecord(g_sx.ev_h1, 0);

    // ---- fork: proj on s2 ----
    cudaStreamWaitEvent(g_sx.s2, g_sx.ev_h1, 0);
    k_proj_part<<<dim3(24, 4, 4), 128, 0, g_sx.s2>>>(W_proj);
    cudaEventRecord(g_sx.ev_proj, g_sx.s2);

    // ---- copy-attention chain on s1 (after zc gemm + h1 + sparse fp16) ----
    cudaStreamWaitEvent(g_sx.s1, g_sx.ev_h1, 0);
    k_csdot<<<512, 256, 0, g_sx.s1>>>();
    k_rowmax<<<Bc, 512, 0, g_sx.s1>>>();
    cudaStreamWaitEvent(g_sx.s1, g_sx.ev_sparse, 0);
    k_zcopy_part<<<dim3(4, Bc, 8), 128, 0, g_sx.s1>>>();
    cudaEventRecord(g_sx.ev_zc, g_sx.s1);

    // ---- join on default ----
    cudaStreamWaitEvent(0, g_sx.ev_proj, 0);
    cudaStreamWaitEvent(0, g_sx.ev_zc, 0);
    k_final<<<Bc, 512>>>(b_proj, out);
}

// round 16
// speedup vs baseline: 1.0794x; 1.0794x over previous
#include <cuda_runtime.h>
#include <cuda_bf16.h>
#include <math.h>
#include <cstdint>

// Problem constants
#define TZc 512
#define Bc  64
#define Hc  512
#define Ec  256
#define Vc  3000
#define Dc  5
#define VTc 3512          // V + TZ
#define GINc 1285         // E + 2H + D
#define XPADc 1288
#define G3c 1536          // 3H
#define ENC_ELEMS 16777216  // 32768*512

// ---------------- scratch (device globals; no allocation allowed) ------------
__device__ float g_accbuf[5 * 32768];
__device__ float g_hw[2 * 32768];
__device__ float g_x[Bc * XPADc];
__device__ float g_gi[Bc * G3c];
__device__ float g_gh[Bc * G3c];
__device__ float g_h1[Bc * Hc];
__device__ float g_ecs[Bc * TZc];
__device__ float g_mrow[Bc];
__device__ float g_zc[32768 * 512];
__device__ float g_ppart[4 * 64 * 3008];   // proj partials [jc][b][v]
__device__ float g_zpart[64 * 8 * 3520];   // zcopy partials [b][tc][v]
__device__ float g_wih[G3c * XPADc];
__device__ __nv_bfloat16 g_wt_hi[3 * 512 * 512];
__device__ __nv_bfloat16 g_wt_lo[3 * 512 * 512];
__device__ __nv_bfloat16 g_enc_hi[2 * ENC_ELEMS];
__device__ __nv_bfloat16 g_enc_lo[2 * ENC_ELEMS];

// ---------------- streams/events (created pre-main, before harness checkpoints)
struct StreamsInit {
    cudaStream_t s1, s2;
    cudaEvent_t ev_root, ev_prepw, ev_encz, ev_encu, ev_wih, ev_h1, ev_zc, ev_proj;
    StreamsInit() {
        cudaStreamCreateWithFlags(&s1, cudaStreamNonBlocking);
        cudaStreamCreateWithFlags(&s2, cudaStreamNonBlocking);
        cudaEventCreateWithFlags(&ev_root, cudaEventDisableTiming);
        cudaEventCreateWithFlags(&ev_prepw, cudaEventDisableTiming);
        cudaEventCreateWithFlags(&ev_encz, cudaEventDisableTiming);
        cudaEventCreateWithFlags(&ev_encu, cudaEventDisableTiming);
        cudaEventCreateWithFlags(&ev_wih, cudaEventDisableTiming);
        cudaEventCreateWithFlags(&ev_h1, cudaEventDisableTiming);
        cudaEventCreateWithFlags(&ev_zc, cudaEventDisableTiming);
        cudaEventCreateWithFlags(&ev_proj, cudaEventDisableTiming);
    }
};
static StreamsInit g_sx;

// ---------------- helpers ------------------------------------------------------
__device__ __forceinline__ float tanh_fast(float x) {
    float y;
    asm("tanh.approx.f32 %0, %1;" : "=f"(y) : "f"(x));
    return y;
}
__device__ __forceinline__ void mma16816(float* c, const uint32_t* a, const uint32_t* b) {
    asm volatile(
        "mma.sync.aligned.m16n8k16.row.col.f32.bf16.bf16.f32 "
        "{%0,%1,%2,%3}, {%4,%5,%6,%7}, {%8,%9}, {%0,%1,%2,%3};"
        : "+f"(c[0]), "+f"(c[1]), "+f"(c[2]), "+f"(c[3])
        : "r"(a[0]), "r"(a[1]), "r"(a[2]), "r"(a[3]), "r"(b[0]), "r"(b[1]));
}
__device__ __forceinline__ uint32_t smem_u32(const void* p) {
    uint32_t a;
    asm("{ .reg .u64 t; cvta.to.shared.u64 t, %1; cvt.u32.u64 %0, t; }" : "=r"(a) : "l"(p));
    return a;
}
__device__ __forceinline__ void ldsm_x4(uint32_t& r0, uint32_t& r1, uint32_t& r2,
                                        uint32_t& r3, uint32_t addr) {
    asm volatile("ldmatrix.sync.aligned.m8n8.x4.shared.b16 {%0,%1,%2,%3}, [%4];"
                 : "=r"(r0), "=r"(r1), "=r"(r2), "=r"(r3) : "r"(addr));
}
__device__ __forceinline__ void cpasync16(uint32_t dst, const void* src) {
    asm volatile("cp.async.cg.shared.global [%0], [%1], 16;" :: "r"(dst), "l"(src));
}

// ---------------- block reductions -------------------------------------------
__device__ __forceinline__ float blockReduceMax(float v, float* sh) {
    #pragma unroll
    for (int o = 16; o; o >>= 1) v = fmaxf(v, __shfl_xor_sync(0xffffffffu, v, o));
    if ((threadIdx.x & 31) == 0) sh[threadIdx.x >> 5] = v;
    __syncthreads();
    float r = sh[0];
    int nw = (blockDim.x + 31) >> 5;
    for (int j = 1; j < nw; j++) r = fmaxf(r, sh[j]);
    __syncthreads();
    return r;
}
__device__ __forceinline__ float blockReduceSum(float v, float* sh) {
    #pragma unroll
    for (int o = 16; o; o >>= 1) v += __shfl_xor_sync(0xffffffffu, v, o);
    if ((threadIdx.x & 31) == 0) sh[threadIdx.x >> 5] = v;
    __syncthreads();
    float r = 0.f;
    int nw = (blockDim.x + 31) >> 5;
    for (int j = 0; j < nw; j++) r += sh[j];
    __syncthreads();
    return r;
}

// ---------------- kernels -----------------------------------------------------

__global__ void k_zero() {
    int i = blockIdx.x * blockDim.x + threadIdx.x;
    if (i < 4 * 32768) g_accbuf[i] = 0.f;
}

__global__ void k_prep_w(const float* __restrict__ Wz, const float* __restrict__ Wu,
                         const float* __restrict__ Wc2) {
    __shared__ float ts[32][33];
    int which = blockIdx.z;
    const float* W = (which == 0) ? (Wz + 512 * 512) : (which == 1) ? (Wu + 512 * 512) : Wc2;
    int k0 = blockIdx.y * 32, n0 = blockIdx.x * 32;
    int tx = threadIdx.x, ty = threadIdx.y;
    #pragma unroll
    for (int j = 0; j < 32; j += 8)
        ts[ty + j][tx] = W[(size_t)(k0 + ty + j) * 512 + n0 + tx];
    __syncthreads();
    __nv_bfloat16* oh = g_wt_hi + (size_t)which * 262144;
    __nv_bfloat16* ol = g_wt_lo + (size_t)which * 262144;
    #pragma unroll
    for (int j = 0; j < 32; j += 8) {
        float x = ts[tx][ty + j];
        __nv_bfloat16 h = __float2bfloat16(x);
        __nv_bfloat16 l = __float2bfloat16(x - __bfloat162float(h));
        size_t idx = (size_t)(n0 + ty + j) * 512 + k0 + tx;
        oh[idx] = h; ol[idx] = l;
    }
}

// 8 elems/thread, 16B stores; `which` selects destination slot
__global__ void __launch_bounds__(256)
k_prep_enc(const float* __restrict__ src, int which) {
    size_t i8 = (size_t)blockIdx.x * 256 + threadIdx.x;   // 8-elem unit, < 2097152
    const float4* s4 = (const float4*)src + i8 * 2;
    float4 v0 = s4[0], v1 = s4[1];
    float xs[8] = {v0.x, v0.y, v0.z, v0.w, v1.x, v1.y, v1.z, v1.w};
    union { uint4 u; __nv_bfloat16 h[8]; } ph, pl;
    #pragma unroll
    for (int j = 0; j < 8; j++) {
        __nv_bfloat16 hh = __float2bfloat16(xs[j]);
        ph.h[j] = hh;
        pl.h[j] = __float2bfloat16(xs[j] - __bfloat162float(hh));
    }
    ((uint4*)(g_enc_hi + (size_t)which * ENC_ELEMS))[i8] = ph.u;
    ((uint4*)(g_enc_lo + (size_t)which * ENC_ELEMS))[i8] = pl.u;
}

__global__ void k_prep_wih(const float* __restrict__ W_ih) {
    int g = blockIdx.x;
    for (int i = threadIdx.x; i < XPADc; i += 256)
        g_wih[(size_t)g * XPADc + i] = (i < GINc) ? W_ih[(size_t)g * GINc + i] : 0.f;
}

__global__ void k_hW(const float* __restrict__ h0,
                     const float* __restrict__ Wz, const float* __restrict__ bz,
                     const float* __restrict__ Wu, const float* __restrict__ bu) {
    int b = blockIdx.x, which = blockIdx.y, k = threadIdx.x;
    const float* W  = which ? Wu : Wz;
    const float* bb = which ? bu : bz;
    float* o = g_hw + which * 32768;
    __shared__ float sh[512];
    sh[k] = h0[b * 512 + k];
    __syncthreads();
    float acc = bb[k];
    #pragma unroll 8
    for (int j = 0; j < 512; j++) acc += sh[j] * W[j * 512 + k];
    o[b * 512 + k] = acc;
}

// ---------------- 2-stage pipelined mma.sync GEMM, warp tile 32x64 ------------
// grid: x = n-tile (4), y = m-tile (512), z = gemm offset; gid = gbase + z
// CTA tile 64(M) x 128(N), 4 warps (2M x 2N), K chunk 64.
#define SA_STRIDE 72
#define SMA (64 * SA_STRIDE)
#define SMB (128 * SA_STRIDE)
#define STG_ELEMS (2 * SMA + 2 * SMB)
#define STG_BYTES (STG_ELEMS * 2)
#define OFF_AH 0
#define OFF_AL SMA
#define OFF_BH (2 * SMA)
#define OFF_BL (2 * SMA + SMB)
#define GEMM_SMEM (2 * STG_BYTES)         // 110592 B
__global__ void __launch_bounds__(128, 2)
k_mma_gemm(const float* __restrict__ vz, const float* __restrict__ vu,
           const float* __restrict__ bc2, int gbase) {
    extern __shared__ char smem_raw[];
    const uint32_t sbase = smem_u32(smem_raw);

    const int tid = threadIdx.x;
    const int wid = tid >> 5;      // 0..3
    const int lane = tid & 31;
    const int gro = lane >> 2;
    const int tig = lane & 3;
    const int wm = wid >> 1;       // 0..1  (M, 32 rows)
    const int wn = wid & 1;        // 0..1  (N, 64 cols)

    const int gid = gbase + blockIdx.z;
    const int n0 = blockIdx.x * 128;
    const int m0 = blockIdx.y * 64;

    const size_t encoff = (gid == 1) ? (size_t)ENC_ELEMS : 0;
    const __nv_bfloat16* AH = g_enc_hi + encoff;
    const __nv_bfloat16* AL = g_enc_lo + encoff;
    const __nv_bfloat16* WtH = g_wt_hi + (size_t)gid * 262144;
    const __nv_bfloat16* WtL = g_wt_lo + (size_t)gid * 262144;

    const int a_row0 = wm * 32 + (lane & 7) + ((lane & 8) ? 8 : 0);
    const int a_koff = (lane & 16) ? 8 : 0;
    const int b_rowbase = wn * 64 + (lane & 7) + ((lane & 16) ? 8 : 0);
    const int b_koff = (lane & 8) ? 8 : 0;

    float c[2][8][4];
    #pragma unroll
    for (int mt = 0; mt < 2; mt++)
        #pragma unroll
        for (int i = 0; i < 8; i++)
            #pragma unroll
            for (int r = 0; r < 4; r++) c[mt][i][r] = 0.f;

    auto load_stage = [&](uint32_t sdst, int kk) {
        #pragma unroll
        for (int i = 0; i < 16; i++) {
            int idx = tid + i * 128;           // 0..2047 : B
            int buf = idx >> 10;
            int line = idx & 1023;
            int row = line >> 3, kq = line & 7;
            uint32_t dst = sdst + (uint32_t)((buf ? OFF_BL : OFF_BH) + row * SA_STRIDE + kq * 8) * 2;
            const __nv_bfloat16* src = (buf ? WtL : WtH) + (size_t)(n0 + row) * 512 + kk + kq * 8;
            cpasync16(dst, src);
        }
        #pragma unroll
        for (int i = 0; i < 8; i++) {
            int idx = tid + i * 128;           // 0..1023 : A
            int buf = idx >> 9;
            int line = idx & 511;
            int row = line >> 3, kq = line & 7;
            uint32_t dst = sdst + (uint32_t)((buf ? OFF_AL : OFF_AH) + row * SA_STRIDE + kq * 8) * 2;
            const __nv_bfloat16* src = (buf ? AL : AH) + (size_t)(m0 + row) * 512 + kk + kq * 8;
            cpasync16(dst, src);
        }
        asm volatile("cp.async.commit_group;");
    };

    load_stage(sbase, 0);
    asm volatile("cp.async.wait_group 0;");
    __syncthreads();

    for (int ck = 0; ck < 8; ck++) {
        const uint32_t scur = sbase + (uint32_t)(ck & 1) * STG_BYTES;
        const uint32_t snxt = sbase + (uint32_t)((ck & 1) ^ 1) * STG_BYTES;
        if (ck < 7) load_stage(snxt, (ck + 1) * 64);
        #pragma unroll
        for (int ks = 0; ks < 4; ks++) {
            uint32_t ah[2][4], al[2][4];
            #pragma unroll
            for (int mt = 0; mt < 2; mt++) {
                uint32_t aoff = (uint32_t)((a_row0 + mt * 16) * SA_STRIDE + ks * 16 + a_koff) * 2;
                ldsm_x4(ah[mt][0], ah[mt][1], ah[mt][2], ah[mt][3], scur + OFF_AH * 2 + aoff);
                ldsm_x4(al[mt][0], al[mt][1], al[mt][2], al[mt][3], scur + OFF_AL * 2 + aoff);
            }
            #pragma unroll
            for (int nt2 = 0; nt2 < 4; nt2++) {
                uint32_t boff = (uint32_t)((b_rowbase + nt2 * 16) * SA_STRIDE + ks * 16 + b_koff) * 2;
                uint32_t b0, b1, b2, b3;
                ldsm_x4(b0, b1, b2, b3, scur + OFF_BH * 2 + boff);
                uint32_t beh[2] = {b0, b1}, boh[2] = {b2, b3};
                #pragma unroll
                for (int mt = 0; mt < 2; mt++) {
                    mma16816(c[mt][nt2 * 2],     ah[mt], beh);
                    mma16816(c[mt][nt2 * 2 + 1], ah[mt], boh);
                    mma16816(c[mt][nt2 * 2],     al[mt], beh);
                    mma16816(c[mt][nt2 * 2 + 1], al[mt], boh);
                }
                ldsm_x4(b0, b1, b2, b3, scur + OFF_BL * 2 + boff);
                uint32_t bel[2] = {b0, b1}, bol[2] = {b2, b3};
                #pragma unroll
                for (int mt = 0; mt < 2; mt++) {
                    mma16816(c[mt][nt2 * 2],     ah[mt], bel);
                    mma16816(c[mt][nt2 * 2 + 1], ah[mt], bol);
                }
            }
        }
        if (ck < 7) asm volatile("cp.async.wait_group 0;");
        __syncthreads();
    }

    if (gid < 2) {
        const int t = blockIdx.y;
        const float* vv = gid ? vu : vz;
        #pragma unroll
        for (int mt = 0; mt < 2; mt++) {
            #pragma unroll
            for (int h = 0; h < 2; h++) {
                int b = wm * 32 + mt * 16 + gro + h * 8;
                const float* bias = g_hw + gid * 32768 + b * 512;
                float s = 0.f;
                #pragma unroll
                for (int nt = 0; nt < 8; nt++) {
                    #pragma unroll
                    for (int j = 0; j < 2; j++) {
                        int n = n0 + wn * 64 + nt * 8 + tig * 2 + j;
                        s += tanh_fast(c[mt][nt][h * 2 + j] + bias[n]) * vv[n];
                    }
                }
                s += __shfl_xor_sync(0xffffffffu, s, 1);
                s += __shfl_xor_sync(0xffffffffu, s, 2);
                if (tig == 0) atomicAdd(&g_accbuf[gid * 32768 + b * 512 + t], s);
            }
        }
    } else {
        float* zs = (float*)smem_raw;   // [64][130]
        #pragma unroll
        for (int mt = 0; mt < 2; mt++) {
            #pragma unroll
            for (int h = 0; h < 2; h++) {
                int r = wm * 32 + mt * 16 + gro + h * 8;
                #pragma unroll
                for (int nt = 0; nt < 8; nt++) {
                    #pragma unroll
                    for (int j = 0; j < 2; j++) {
                        int nl = wn * 64 + nt * 8 + tig * 2 + j;
                        zs[r * 130 + nl] = tanhf(c[mt][nt][h * 2 + j] + bc2[n0 + nl]);
                    }
                }
            }
        }
        __syncthreads();
        for (int i = tid; i < 64 * 32; i += 128) {
            int r = i >> 5, c4 = (i & 31) * 4;
            float4 v = make_float4(zs[r * 130 + c4], zs[r * 130 + c4 + 1],
                                   zs[r * 130 + c4 + 2], zs[r * 130 + c4 + 3]);
            *(float4*)(g_zc + (size_t)(m0 + r) * 512 + n0 + c4) = v;
        }
    }
}

// fused softmax + ctx
__global__ void k_ctx(const float* __restrict__ z_enc, const float* __restrict__ u_enc) {
    int which = blockIdx.z;
    int b  = blockIdx.y;
    int t0 = blockIdx.x * 64;
    int h  = threadIdx.x;
    const float* enc = which ? u_enc : z_enc;
    const float* e   = g_accbuf + which * 32768 + b * 512;
    float* ctx = g_accbuf + (2 + which) * 32768 + b * 512;
    __shared__ float shr[16];
    __shared__ float sa[64];
    float x = e[h];
    float m = blockReduceMax(x, shr);
    float ex = expf(x - m);
    float ssum = blockReduceSum(ex, shr);
    if (h >= t0 && h < t0 + 64) sa[h - t0] = ex / ssum;
    __syncthreads();
    float s = 0.f;
    #pragma unroll 8
    for (int tt = 0; tt < 64; tt++)
        s += sa[tt] * enc[((size_t)(t0 + tt) * 64 + b) * 512 + h];
    atomicAdd(&ctx[h], s);
}

__global__ void k_assemble(const float* __restrict__ emb, const int* __restrict__ mt,
                           const float* __restrict__ degree) {
    int b = blockIdx.x, tid = threadIdx.x;
    float* xr = g_x + b * XPADc;
    const float* ctxz = g_accbuf + 2 * 32768 + b * 512;
    const float* ctxu = g_accbuf + 3 * 32768 + b * 512;
    int m = mt[b];
    if (tid < 256) xr[tid] = emb[(size_t)m * Ec + tid];
    xr[256 + tid] = ctxu[tid];
    xr[768 + tid] = ctxz[tid];
    if (tid < 8) xr[1280 + tid] = (tid < 5) ? degree[b * Dc + tid] : 0.f;
}

__global__ void __launch_bounds__(256)
k_gates(const float* __restrict__ W_hh,
        const float* __restrict__ b_ih, const float* __restrict__ b_hh,
        const float* __restrict__ h0) {
    int b = threadIdx.x & 63;
    int g = blockIdx.x * 4 + (threadIdx.x >> 6);
    const float4* xr = (const float4*)(g_x + b * XPADc);
    const float4* wr = (const float4*)(g_wih + (size_t)g * XPADc);
    float a0 = 0.f, a1 = 0.f, a2 = 0.f, a3 = 0.f;
    #pragma unroll 2
    for (int j = 0; j < 320; j += 4) {
        float4 w0 = wr[j], x0 = xr[j];
        float4 w1 = wr[j+1], x1 = xr[j+1];
        float4 w2 = wr[j+2], x2 = xr[j+2];
        float4 w3 = wr[j+3], x3 = xr[j+3];
        a0 += w0.x*x0.x + w0.y*x0.y + w0.z*x0.z + w0.w*x0.w;
        a1 += w1.x*x1.x + w1.y*x1.y + w1.z*x1.z + w1.w*x1.w;
        a2 += w2.x*x2.x + w2.y*x2.y + w2.z*x2.z + w2.w*x2.w;
        a3 += w3.x*x3.x + w3.y*x3.y + w3.z*x3.z + w3.w*x3.w;
    }
    {
        float4 w0 = wr[320], x0 = xr[320];
        float4 w1 = wr[321], x1 = xr[321];
        a0 += w0.x*x0.x + w0.y*x0.y + w0.z*x0.z + w0.w*x0.w;
        a1 += w1.x*x1.x + w1.y*x1.y + w1.z*x1.z + w1.w*x1.w;
    }
    g_gi[b * G3c + g] = b_ih[g] + (a0 + a1) + (a2 + a3);

    const float4* hr = (const float4*)(h0 + b * 512);
    const float4* wh = (const float4*)(W_hh + (size_t)g * 512);
    a0 = a1 = a2 = a3 = 0.f;
    #pragma unroll 2
    for (int j = 0; j < 128; j += 4) {
        float4 w0 = wh[j], x0 = hr[j];
        float4 w1 = wh[j+1], x1 = hr[j+1];
        float4 w2 = wh[j+2], x2 = hr[j+2];
        float4 w3 = wh[j+3], x3 = hr[j+3];
        a0 += w0.x*x0.x + w0.y*x0.y + w0.z*x0.z + w0.w*x0.w;
        a1 += w1.x*x1.x + w1.y*x1.y + w1.z*x1.z + w1.w*x1.w;
        a2 += w2.x*x2.x + w2.y*x2.y + w2.z*x2.z + w2.w*x2.w;
        a3 += w3.x*x3.x + w3.y*x3.y + w3.z*x3.z + w3.w*x3.w;
    }
    g_gh[b * G3c + g] = b_hh[g] + (a0 + a1) + (a2 + a3);
}

__global__ void k_h1(const float* __restrict__ h0, float* __restrict__ out) {
    int b = blockIdx.x, h = threadIdx.x;
    float ir = g_gi[b * G3c + h],        hr = g_gh[b * G3c + h];
    float iz = g_gi[b * G3c + 512 + h],  hz = g_gh[b * G3c + 512 + h];
    float in_ = g_gi[b * G3c + 1024 + h], hn = g_gh[b * G3c + 1024 + h];
    float r = 1.f / (1.f + expf(-(ir + hr)));
    float z = 1.f / (1.f + expf(-(iz + hz)));
    float n = tanhf(in_ + r * hn);
    float hv = (1.f - z) * n + z * h0[b * 512 + h];
    g_h1[b * 512 + h] = hv;
    out[Bc * VTc + b * 512 + h] = hv;
    out[Bc * VTc + Bc * 512 + b * 512 + h] = hv;
}

__global__ void __launch_bounds__(256)
k_csdot() {
    int t = blockIdx.x;
    int q = threadIdx.x & 3;
    int b = threadIdx.x >> 2;
    const float4* zr = (const float4*)(g_zc + ((size_t)t * 64 + b) * 512);
    const float4* hr = (const float4*)(g_h1 + b * 512);
    float s = 0.f;
    #pragma unroll 8
    for (int i = 0; i < 32; i++) {
        int idx = i * 4 + q;
        float4 a = zr[idx], h = hr[idx];
        s += a.x * h.x + a.y * h.y + a.z * h.z + a.w * h.w;
    }
    s += __shfl_xor_sync(0xffffffffu, s, 1);
    s += __shfl_xor_sync(0xffffffffu, s, 2);
    if (q == 0) g_accbuf[4 * 32768 + b * 512 + t] = s;
}

__global__ void __launch_bounds__(128)
k_proj_part(const float* __restrict__ W_proj) {
    __shared__ float sx[16][385];
    int b0 = blockIdx.y * 16;
    int jc = blockIdx.z;
    int j0 = jc * 384;
    int tid = threadIdx.x;
    for (int i = tid; i < 16 * 384; i += 128) {
        int bl = i / 384, jj = i % 384;
        int j = j0 + jj;
        int b = b0 + bl;
        float v;
        if (j < 512)       v = g_accbuf[2 * 32768 + b * 512 + j];
        else if (j < 1024) v = g_accbuf[3 * 32768 + b * 512 + (j - 512)];
        else               v = g_h1[b * 512 + (j - 1024)];
        sx[bl][jj] = v;
    }
    __syncthreads();
    int v = blockIdx.x * 128 + tid;
    if (v >= Vc) return;
    float acc[16];
    #pragma unroll
    for (int bl = 0; bl < 16; bl++) acc[bl] = 0.f;
    #pragma unroll 4
    for (int jj = 0; jj < 384; jj++) {
        float w = W_proj[(size_t)(j0 + jj) * Vc + v];
        #pragma unroll
        for (int bl = 0; bl < 16; bl++) acc[bl] += sx[bl][jj] * w;
    }
    #pragma unroll
    for (int bl = 0; bl < 16; bl++)
        g_ppart[(size_t)(jc * 64 + b0 + bl) * 3008 + v] = acc[bl];
}

__global__ void k_rowmax() {
    __shared__ float sh[16];
    int b = blockIdx.x, t = threadIdx.x;
    float c = g_accbuf[4 * 32768 + b * 512 + t];
    float m = blockReduceMax(c, sh);
    g_ecs[b * 512 + t] = expf(c - m);
    if (t == 0) g_mrow[b] = m;
}

__global__ void __launch_bounds__(128)
k_zcopy_part(const float* __restrict__ sparse) {
    __shared__ float se[64];
    int b = blockIdx.y, tc = blockIdx.z;
    int tid = threadIdx.x;
    if (tid < 64) se[tid] = g_ecs[b * 512 + tc * 64 + tid];
    __syncthreads();
    int v4 = blockIdx.x * 128 + tid;
    if (v4 >= 878) return;
    const float4* sp = (const float4*)(sparse + (size_t)b * TZc * VTc)
                       + (size_t)(tc * 64) * 878 + v4;
    float4 s = make_float4(0.f, 0.f, 0.f, 0.f);
    #pragma unroll 8
    for (int t = 0; t < 64; t++) {
        float4 x = sp[(size_t)t * 878];
        float e = se[t];
        s.x += e * x.x; s.y += e * x.y; s.z += e * x.z; s.w += e * x.w;
    }
    ((float4*)(g_zpart + (size_t)(b * 8 + tc) * 3520))[v4] = s;
}

__global__ void k_final(const float* __restrict__ b_proj, float* __restrict__ out) {
    __shared__ float sh[16];
    int b = blockIdx.x, tid = threadIdx.x;
    float gl[6], cl[7];
    #pragma unroll
    for (int i = 0; i < 6; i++) {
        int v = tid + i * 512;
        if (v < Vc) {
            float s = b_proj[v];
            #pragma unroll
            for (int jc = 0; jc < 4; jc++) s += g_ppart[(size_t)(jc * 64 + b) * 3008 + v];
            gl[i] = s;
        } else gl[i] = -1e30f;
    }
    float mb = g_mrow[b];
    #pragma unroll
    for (int i = 0; i < 7; i++) {
        int v = tid + i * 512;
        if (v < VTc) {
            float s = 0.f;
            #pragma unroll
            for (int tc = 0; tc < 8; tc++) s += g_zpart[(size_t)(b * 8 + tc) * 3520 + v];
            cl[i] = logf(s) + mb;
        } else cl[i] = -1e30f;
    }
    float m = -1e30f;
    #pragma unroll
    for (int i = 0; i < 6; i++) m = fmaxf(m, gl[i]);
    #pragma unroll
    for (int i = 0; i < 7; i++) m = fmaxf(m, cl[i]);
    m = blockReduceMax(m, sh);
    float s = 0.f;
    #pragma unroll
    for (int i = 0; i < 6; i++) s += expf(gl[i] - m);
    #pragma unroll
    for (int i = 0; i < 7; i++) s += expf(cl[i] - m);
    s = blockReduceSum(s, sh);
    float inv = 1.f / s;
    float* op = out + (size_t)b * VTc;
    #pragma unroll
    for (int i = 0; i < 7; i++) {
        int v = tid + i * 512;
        if (v < Vc)        op[v] = (expf(gl[i] - m) + expf(cl[i] - m)) * inv;
        else if (v < VTc)  op[v] = expf(cl[i] - m) * inv;
    }
}

// ---------------- launch ------------------------------------------------------
extern "C" void kernel_launch(void* const* d_in, const int* in_sizes, int n_in,
                              void* d_out, int out_size) {
    (void)in_sizes; (void)n_in; (void)out_size;
    const float* z_enc  = (const float*)d_in[0];
    const float* u_enc  = (const float*)d_in[1];
    const int*   mt     = (const int*)  d_in[2];
    const float* degree = (const float*)d_in[3];
    const float* h0     = (const float*)d_in[4];
    const float* sparse = (const float*)d_in[5];
    const float* emb    = (const float*)d_in[6];
    const float* Wz     = (const float*)d_in[7];
    const float* bz     = (const float*)d_in[8];
    const float* vz     = (const float*)d_in[9];
    const float* Wu     = (const float*)d_in[10];
    const float* bu     = (const float*)d_in[11];
    const float* vu     = (const float*)d_in[12];
    const float* W_ih   = (const float*)d_in[13];
    const float* W_hh   = (const float*)d_in[14];
    const float* b_ih   = (const float*)d_in[15];
    const float* b_hh   = (const float*)d_in[16];
    const float* W_proj = (const float*)d_in[17];
    const float* b_proj = (const float*)d_in[18];
    const float* Wc2    = (const float*)d_in[19];
    const float* bc2    = (const float*)d_in[20];
    float* out = (float*)d_out;

    cudaFuncSetAttribute(k_mma_gemm, cudaFuncAttributeMaxDynamicSharedMemorySize, GEMM_SMEM);

    // ---- fork root: side streams join capture via origin-stream event
    cudaEventRecord(g_sx.ev_root, 0);
    cudaStreamWaitEvent(g_sx.s1, g_sx.ev_root, 0);
    cudaStreamWaitEvent(g_sx.s2, g_sx.ev_root, 0);

    // default: weight transpose/split + hW + zero (zero must precede gemm atomics)
    k_prep_w<<<dim3(16, 16, 3), dim3(32, 8)>>>(Wz, Wu, Wc2);
    cudaEventRecord(g_sx.ev_prepw, 0);
    k_hW<<<dim3(Bc, 2), 512>>>(h0, Wz, bz, Wu, bu);
    k_zero<<<256, 512>>>();
    // s1: encoder z split
    k_prep_enc<<<8192, 256, 0, g_sx.s1>>>(z_enc, 0);
    cudaEventRecord(g_sx.ev_encz, g_sx.s1);
    // s2: encoder u split FIRST (gates the attention launch), then wih repack
    k_prep_enc<<<8192, 256, 0, g_sx.s2>>>(u_enc, 1);
    cudaEventRecord(g_sx.ev_encu, g_sx.s2);
    k_prep_wih<<<G3c, 256, 0, g_sx.s2>>>(W_ih);
    cudaEventRecord(g_sx.ev_wih, g_sx.s2);

    // ---- zc gemm on s1 (needs enc_z + wt[2]) ----
    cudaStreamWaitEvent(g_sx.s1, g_sx.ev_prepw, 0);
    k_mma_gemm<<<dim3(4, 512, 1), 128, GEMM_SMEM, g_sx.s1>>>(vz, vu, bc2, 2);

    // ---- attention gemms + GRU chain on default ----
    cudaStreamWaitEvent(0, g_sx.ev_encz, 0);
    cudaStreamWaitEvent(0, g_sx.ev_encu, 0);
    k_mma_gemm<<<dim3(4, 512, 2), 128, GEMM_SMEM>>>(vz, vu, bc2, 0);
    k_ctx<<<dim3(8, Bc, 2), 512>>>(z_enc, u_enc);
    k_assemble<<<Bc, 512>>>(emb, mt, degree);
    cudaStreamWaitEvent(0, g_sx.ev_wih, 0);
    k_gates<<<G3c / 4, 256>>>(W_hh, b_ih, b_hh, h0);
    k_h1<<<Bc, 512>>>(h0, out);
    cudaEventRecord(g_sx.ev_h1, 0);

    // ---- fork: proj on s2 ----
    cudaStreamWaitEvent(g_sx.s2, g_sx.ev_h1, 0);
    k_proj_part<<<dim3(24, 4, 4), 128, 0, g_sx.s2>>>(W_proj);
    cudaEventRecord(g_sx.ev_proj, g_sx.s2);

    // ---- copy-attention chain on s1 (after zc gemm + h1) ----
    cudaStreamWaitEvent(g_sx.s1, g_sx.ev_h1, 0);
    k_csdot<<<512, 256, 0, g_sx.s1>>>();
    k_rowmax<<<Bc, 512, 0, g_sx.s1>>>();
    k_zcopy_part<<<dim3(7, Bc, 8), 128, 0, g_sx.s1>>>(sparse);
    cudaEventRecord(g_sx.ev_zc, g_sx.s1);

    // ---- join on default ----
    cudaStreamWaitEvent(0, g_sx.ev_proj, 0);
    cudaStreamWaitEvent(0, g_sx.ev_zc, 0);
    k_final<<<Bc, 512>>>(b_proj, out);
}